// round 14
// baseline (speedup 1.0000x reference)
#include <cuda_runtime.h>
#include <math.h>
#include <stdint.h>

// ---------------- problem constants ----------------
#define B_     2
#define L_     1024
#define T_     2048            // B_*L_
#define DM     1024            // d_model
#define DIN    2048            // d_inner
#define NH     32              // nheads
#define HD     64              // headdim
#define DS     128             // d_state
#define CONVD  2304            // DIN + 2*DS
#define DPROJ  4384            // 2*DIN + 2*DS + NH
#define INTER  2752
#define EPSF   1e-6f
#define TS     16              // scan time-chunk
#define NC     (L_/TS)         // 64 chunks (even)
#define NOSPLIT 0x40000000

#define GEMM_SMEM (4 * 128 * 36 * 4)   // 2 stages x (As+Bs) x 128x36 floats = 73728 B

// ---------------- scratch (device globals; no allocation allowed) ----------------
__device__ float g_xn  [(size_t)T_*DM];
__device__ float g_zx  [(size_t)T_*DPROJ];
__device__ float g_cv  [(size_t)T_*CONVD];
__device__ float g_y0  [(size_t)T_*DIN];
__device__ float g_y1  [(size_t)T_*DIN];
__device__ float g_y2  [(size_t)T_*DIN];
__device__ float g_y3  [(size_t)T_*DIN];
__device__ float g_yn  [(size_t)T_*DIN];
__device__ float g_x2  [(size_t)T_*DM];
__device__ float g_hn  [(size_t)T_*DM];
__device__ float g_gate[(size_t)T_*INTER];
__device__ float g_up  [(size_t)T_*INTER];
__device__ float g_ps  [(size_t)3*T_*DM];   // split-K partials (reused out_proj/down)

// ---------------- helpers ----------------
__device__ __forceinline__ float siluf(float x) {
    return x / (1.f + __expf(-x));
}

__device__ __forceinline__ uint32_t f2tf32(float x) {
    uint32_t r;
    asm("cvt.rna.tf32.f32 %0, %1;" : "=r"(r) : "f"(x));
    return r;
}

__device__ __forceinline__ uint32_t smem_u32(const void* p) {
    return (uint32_t)__cvta_generic_to_shared(p);
}

__device__ __forceinline__ void cp16(uint32_t dst, const void* src, int bytes) {
    asm volatile("cp.async.ca.shared.global [%0], [%1], 16, %2;"
                 :: "r"(dst), "l"(src), "r"(bytes));
}

__device__ __forceinline__ float block_reduce_sum(float v) {
    __shared__ float sh[32];
    int lane = threadIdx.x & 31, w = threadIdx.x >> 5;
    #pragma unroll
    for (int o = 16; o; o >>= 1) v += __shfl_xor_sync(0xffffffffu, v, o);
    if (lane == 0) sh[w] = v;
    __syncthreads();
    int nw = blockDim.x >> 5;
    v = (threadIdx.x < (unsigned)nw) ? sh[threadIdx.x] : 0.f;
    if (w == 0) {
        #pragma unroll
        for (int o = 16; o; o >>= 1) v += __shfl_xor_sync(0xffffffffu, v, o);
        if (lane == 0) sh[0] = v;
    }
    __syncthreads();
    return sh[0];
}

// ---------------- rmsnorm over D=1024 ----------------
__global__ void rmsnorm1024_k(const float* __restrict__ x, const float* __restrict__ w,
                              float* __restrict__ o) {
    int row = blockIdx.x;
    int i = threadIdx.x * 4;
    const float4 v = *(const float4*)(x + (size_t)row * DM + i);
    float ss = v.x*v.x + v.y*v.y + v.z*v.z + v.w*v.w;
    ss = block_reduce_sum(ss);
    float sc = rsqrtf(ss * (1.f / DM) + EPSF);
    float4 wv = *(const float4*)(w + i);
    float4 r;
    r.x = v.x * sc * wv.x; r.y = v.y * sc * wv.y;
    r.z = v.z * sc * wv.z; r.w = v.w * sc * wv.w;
    *(float4*)(o + (size_t)row * DM + i) = r;
}

// ---- combine split-K partials + residual, then fused post-rmsnorm ----
// x2 = ps0+ps1+ps2 + res ; hn = rmsnorm(x2) * w
__global__ void combine_norm_k(const float* __restrict__ ps, const float* __restrict__ res,
                               const float* __restrict__ w,
                               float* __restrict__ x2, float* __restrict__ hn) {
    int row = blockIdx.x;
    int i = threadIdx.x * 4;
    size_t off = (size_t)row * DM + i;
    float4 a0 = *(const float4*)(ps + off);
    float4 a1 = *(const float4*)(ps + (size_t)T_ * DM + off);
    float4 a2 = *(const float4*)(ps + (size_t)2 * T_ * DM + off);
    float4 rv = *(const float4*)(res + off);
    float4 v;
    v.x = (a0.x + a1.x) + (a2.x + rv.x);
    v.y = (a0.y + a1.y) + (a2.y + rv.y);
    v.z = (a0.z + a1.z) + (a2.z + rv.z);
    v.w = (a0.w + a1.w) + (a2.w + rv.w);
    *(float4*)(x2 + off) = v;
    float ss = v.x*v.x + v.y*v.y + v.z*v.z + v.w*v.w;
    ss = block_reduce_sum(ss);
    float sc = rsqrtf(ss * (1.f / DM) + EPSF);
    float4 wv = *(const float4*)(w + i);
    float4 r;
    r.x = v.x * sc * wv.x; r.y = v.y * sc * wv.y;
    r.z = v.z * sc * wv.z; r.w = v.w * sc * wv.w;
    *(float4*)(hn + off) = r;
}

// ---- final combine: out = ps0+ps1+ps2 + x2 ----
__global__ void combine_k(const float* __restrict__ ps, const float* __restrict__ res,
                          float* __restrict__ out) {
    int idx = blockIdx.x * blockDim.x + threadIdx.x;
    size_t off = (size_t)idx * 4;
    float4 a0 = *(const float4*)(ps + off);
    float4 a1 = *(const float4*)(ps + (size_t)T_ * DM + off);
    float4 a2 = *(const float4*)(ps + (size_t)2 * T_ * DM + off);
    float4 rv = *(const float4*)(res + off);
    float4 v;
    v.x = (a0.x + a1.x) + (a2.x + rv.x);
    v.y = (a0.y + a1.y) + (a2.y + rv.y);
    v.z = (a0.z + a1.z) + (a2.z + rv.z);
    v.w = (a0.w + a1.w) + (a2.w + rv.w);
    *(float4*)(out + off) = v;
}

// ---------- gated rmsnorm: out = rmsnorm((y0+y1+y2+y3) * silu(z)) * w ----------
__global__ void gated_norm_k(const float* __restrict__ y0, const float* __restrict__ y1,
                             const float* __restrict__ y2, const float* __restrict__ y3,
                             const float* __restrict__ zx,
                             const float* __restrict__ w, float* __restrict__ o) {
    int row = blockIdx.x;
    float vals[8];
    float ss = 0.f;
    #pragma unroll
    for (int c = 0; c < 2; c++) {
        int i = threadIdx.x * 4 + c * 1024;
        float4 ya = *(const float4*)(y0 + (size_t)row * DIN + i);
        float4 yb = *(const float4*)(y1 + (size_t)row * DIN + i);
        float4 yc = *(const float4*)(y2 + (size_t)row * DIN + i);
        float4 yd = *(const float4*)(y3 + (size_t)row * DIN + i);
        float4 zv = *(const float4*)(zx + (size_t)row * DPROJ + i);
        float a  = ((ya.x + yb.x) + (yc.x + yd.x)) * siluf(zv.x);
        float b  = ((ya.y + yb.y) + (yc.y + yd.y)) * siluf(zv.y);
        float cc = ((ya.z + yb.z) + (yc.z + yd.z)) * siluf(zv.z);
        float d  = ((ya.w + yb.w) + (yc.w + yd.w)) * siluf(zv.w);
        vals[c*4+0]=a; vals[c*4+1]=b; vals[c*4+2]=cc; vals[c*4+3]=d;
        ss += a*a + b*b + cc*cc + d*d;
    }
    ss = block_reduce_sum(ss);
    float sc = rsqrtf(ss * (1.f / DIN) + EPSF);
    #pragma unroll
    for (int c = 0; c < 2; c++) {
        int i = threadIdx.x * 4 + c * 1024;
        float4 wv = *(const float4*)(w + i);
        float4 r;
        r.x = vals[c*4+0] * sc * wv.x; r.y = vals[c*4+1] * sc * wv.y;
        r.z = vals[c*4+2] * sc * wv.z; r.w = vals[c*4+3] * sc * wv.w;
        *(float4*)(o + (size_t)row * DIN + i) = r;
    }
}

// ---------------- causal depthwise conv (width 4) + bias + silu ----------------
__global__ void conv_k(const float* __restrict__ zx, const float* __restrict__ w,
                       const float* __restrict__ bias, float* __restrict__ out) {
    int idx = blockIdx.x * blockDim.x + threadIdx.x;
    if (idx >= T_ * CONVD) return;
    int c   = idx % CONVD;
    int tok = idx / CONVD;
    int l   = tok % L_;
    const float* base = zx + (size_t)tok * DPROJ + DIN + c;
    float w0 = w[c*4+0], w1 = w[c*4+1], w2 = w[c*4+2], w3 = w[c*4+3];
    float acc = bias[c];
    if (l >= 3) acc += base[-(ptrdiff_t)3*DPROJ] * w0;
    if (l >= 2) acc += base[-(ptrdiff_t)2*DPROJ] * w1;
    if (l >= 1) acc += base[-(ptrdiff_t)1*DPROJ] * w2;
    acc += base[0] * w3;
    out[idx] = siluf(acc);
}

// ---------------- selective scan: 4-way state split, 512 blocks (R11 WIN) ----------
__global__ void __launch_bounds__(256) scan_k(const float* __restrict__ cv,
                                              const float* __restrict__ zx,
                                              const float* __restrict__ dt_bias,
                                              const float* __restrict__ A_log,
                                              const float* __restrict__ Dv,
                                              float* __restrict__ yA,
                                              float* __restrict__ yB,
                                              float* __restrict__ yC,
                                              float* __restrict__ yD) {
    int bid = blockIdx.x;
    int ns  = bid & 3;
    int ps  = (bid >> 2) & 1;
    int h   = (bid >> 3) & 31;
    int b   = bid >> 8;
    int tid = threadIdx.x;
    int pl  = tid >> 3;          // 0..31
    int nl  = tid & 7;           // 0..7
    int nb  = nl * 4;            // state offset within 32-slice

    __shared__ float sDt[L_];
    __shared__ float sDA[L_];
    __shared__ float sB0[TS][36], sB1[TS][36];
    __shared__ float sC0[TS][36], sC1[TS][36];
    __shared__ float sX0[TS][32], sX1[TS][32];

    float Ah   = -__expf(A_log[h]);
    float Dh   = Dv[h];
    float bias = dt_bias[h];

    {
        const float* dptr = zx + (size_t)b * L_ * DPROJ + (DPROJ - NH) + h;
        for (int t = tid; t < L_; t += 256) {
            float v  = dptr[(size_t)t * DPROJ] + bias;
            float dt = (v > 20.f) ? v : log1pf(__expf(v));
            sDt[t] = dt;
            sDA[t] = __expf(dt * Ah);
        }
    }

    const float* bcbase = cv + (size_t)b * L_ * CONVD + DIN + ns * 32;  // B slice; C at +DS
    const float* xbase  = cv + (size_t)b * L_ * CONVD + h * HD + ps * 32;

    auto stage = [&](int c, float (*SB)[36], float (*SC)[36], float (*SX)[32]) {
        int t0 = c * TS;
        {   // B|C: 16 tokens x (8+8) float4 = 256 loads, one per thread
            int t = tid >> 4;
            int j = tid & 15;
            const float* src = bcbase + (size_t)(t0 + t) * CONVD
                             + ((j < 8) ? (j * 4) : (DS + (j - 8) * 4));
            float4 v = *(const float4*)src;
            if (j < 8) *(float4*)&SB[t][j * 4] = v;
            else       *(float4*)&SC[t][(j - 8) * 4] = v;
        }
        if (tid < 128) {         // X: 16 tokens x 8 float4
            int t = tid >> 3, j = tid & 7;
            *(float4*)&SX[t][j * 4] =
                *(const float4*)(xbase + (size_t)(t0 + t) * CONVD + j * 4);
        }
    };

    float hs[4];
    #pragma unroll
    for (int i = 0; i < 4; i++) hs[i] = 0.f;

    float* ypart = (ns == 0) ? yA : ((ns == 1) ? yB : ((ns == 2) ? yC : yD));
    float* yptr  = ypart + (size_t)b * L_ * DIN + h * HD + ps * 32 + pl;
    bool writer  = (nl == 0);
    float Dterm  = (ns == 0) ? Dh : 0.f;

    auto compute = [&](int c, float (*SB)[36], float (*SC)[36], float (*SX)[32]) {
        #pragma unroll
        for (int tt = 0; tt < TS; tt++) {
            int t = c * TS + tt;
            float dt  = sDt[t];
            float dA  = sDA[t];
            float xv  = SX[tt][pl];
            float dtx = dt * xv;

            float4 bb = *(const float4*)&SB[tt][nb];
            float4 cc = *(const float4*)&SC[tt][nb];

            float yp0 = 0.f, yp1 = 0.f;
            hs[0] = fmaf(hs[0], dA, dtx * bb.x); yp0 = fmaf(hs[0], cc.x, yp0);
            hs[1] = fmaf(hs[1], dA, dtx * bb.y); yp1 = fmaf(hs[1], cc.y, yp1);
            hs[2] = fmaf(hs[2], dA, dtx * bb.z); yp0 = fmaf(hs[2], cc.z, yp0);
            hs[3] = fmaf(hs[3], dA, dtx * bb.w); yp1 = fmaf(hs[3], cc.w, yp1);

            float yp = yp0 + yp1;
            yp += __shfl_xor_sync(0xffffffffu, yp, 1);
            yp += __shfl_xor_sync(0xffffffffu, yp, 2);
            yp += __shfl_xor_sync(0xffffffffu, yp, 4);
            if (writer)
                yptr[(size_t)t * DIN] = yp + Dterm * xv;
        }
    };

    stage(0, sB0, sC0, sX0);
    __syncthreads();

    for (int c = 0; c < NC; c += 2) {
        stage(c + 1, sB1, sC1, sX1);
        compute(c, sB0, sC0, sX0);
        __syncthreads();
        if (c + 2 < NC) stage(c + 2, sB0, sC0, sX0);
        compute(c + 1, sB1, sC1, sX1);
        __syncthreads();
    }
}

// ---------------- tf32 tensor-core GEMM, cp.async 2-stage, 512 threads ------------
// C[M,N] = A[M,K] * B[N,K]^T (+ Res). 128x128 block tile, BK=32,
// 16 warps (4x4), warp tile 32x32, mma.sync.m16n8k8 tf32.
// Dual-output fusion via nsplit (blockIdx.x >= nsplit -> Bm2/C2).
// Split-K via kchunks: blockIdx.z selects k-tile range, writes partial at
// C + z*pstride (Res must be null when kchunks > 1).
__global__ void __launch_bounds__(512) gemm_tf32(const float* __restrict__ A,
                                                 const float* __restrict__ Bm,
                                                 const float* __restrict__ Bm2,
                                                 const float* __restrict__ Res,
                                                 float* __restrict__ C,
                                                 float* __restrict__ C2,
                                                 int M, int N, int K, int nsplit,
                                                 int kchunks, size_t pstride) {
    extern __shared__ float dsm[];
    float* AsBase = dsm;                       // [2][128][36]
    float* BsBase = dsm + 2 * 128 * 36;        // [2][128][36]

    int tid  = threadIdx.x;
    int bm   = blockIdx.y;
    int bn   = blockIdx.x;
    int z    = blockIdx.z;
    const float* Bw = Bm;
    float* Cw = C;
    if (bn >= nsplit) { bn -= nsplit; Bw = Bm2; Cw = C2; }
    Cw += (size_t)z * pstride;

    int wid  = tid >> 5;
    int lane = tid & 31;
    int wm   = wid >> 2;         // 0..3
    int wn   = wid & 3;          // 0..3
    int g    = lane >> 2;        // 0..7
    int tg   = lane & 3;         // 0..3

    int srow = tid >> 2;               // 0..127 (4 threads per row)
    int sc4  = (tid & 3) * 2;          // first float4 index (0,2,4,6)

    const float* Aab = A + (size_t)(bm * 128 + srow) * K + sc4 * 4;
    int nrow = bn * 128 + srow;
    const float* Bab = Bw + (size_t)nrow * K + sc4 * 4;
    int nvbytes = (nrow < N) ? 16 : 0;

    float acc[2][4][4];
    #pragma unroll
    for (int mi = 0; mi < 2; mi++)
        #pragma unroll
        for (int ni = 0; ni < 4; ni++)
            #pragma unroll
            for (int r = 0; r < 4; r++) acc[mi][ni][r] = 0.f;

    int nk_tot = K >> 5;
    int k0 = (int)((long)nk_tot * z / kchunks);
    int k1 = (int)((long)nk_tot * (z + 1) / kchunks);

    float* Asw = AsBase + (size_t)srow * 36 + sc4 * 4;   // + buf*128*36
    float* Bsw = BsBase + (size_t)srow * 36 + sc4 * 4;

    auto stage = [&](int kt, int buf) {
        const float* a = Aab + (size_t)kt * 32;
        const float* b = Bab + (size_t)kt * 32;
        float* ad = Asw + (size_t)buf * 128 * 36;
        float* bd = Bsw + (size_t)buf * 128 * 36;
        #pragma unroll
        for (int q = 0; q < 2; q++) {
            cp16(smem_u32(ad + q * 4), a + q * 4, 16);
            cp16(smem_u32(bd + q * 4), b + q * 4, nvbytes);
        }
        asm volatile("cp.async.commit_group;" ::: "memory");
    };

    stage(k0, 0);

    for (int kt = k0; kt < k1; kt++) {
        int buf = (kt - k0) & 1;
        asm volatile("cp.async.wait_group 0;" ::: "memory");
        __syncthreads();
        if (kt + 1 < k1) stage(kt + 1, buf ^ 1);

        const float (*AsT)[36] = (const float(*)[36])(AsBase + (size_t)buf * 128 * 36);
        const float (*BsT)[36] = (const float(*)[36])(BsBase + (size_t)buf * 128 * 36);

        #pragma unroll
        for (int ks = 0; ks < 4; ks++) {
            int kk = ks * 8;
            uint32_t af[2][4];
            #pragma unroll
            for (int mi = 0; mi < 2; mi++) {
                int m0 = wm * 32 + mi * 16;
                af[mi][0] = f2tf32(AsT[m0 + g    ][kk + tg    ]);
                af[mi][1] = f2tf32(AsT[m0 + g + 8][kk + tg    ]);
                af[mi][2] = f2tf32(AsT[m0 + g    ][kk + tg + 4]);
                af[mi][3] = f2tf32(AsT[m0 + g + 8][kk + tg + 4]);
            }
            uint32_t bf[4][2];
            #pragma unroll
            for (int ni = 0; ni < 4; ni++) {
                int n0 = wn * 32 + ni * 8;
                bf[ni][0] = f2tf32(BsT[n0 + g][kk + tg    ]);
                bf[ni][1] = f2tf32(BsT[n0 + g][kk + tg + 4]);
            }
            #pragma unroll
            for (int mi = 0; mi < 2; mi++)
                #pragma unroll
                for (int ni = 0; ni < 4; ni++) {
                    asm volatile(
                        "mma.sync.aligned.m16n8k8.row.col.f32.tf32.tf32.f32 "
                        "{%0,%1,%2,%3}, {%4,%5,%6,%7}, {%8,%9}, {%0,%1,%2,%3};"
                        : "+f"(acc[mi][ni][0]), "+f"(acc[mi][ni][1]),
                          "+f"(acc[mi][ni][2]), "+f"(acc[mi][ni][3])
                        : "r"(af[mi][0]), "r"(af[mi][1]), "r"(af[mi][2]), "r"(af[mi][3]),
                          "r"(bf[ni][0]), "r"(bf[ni][1]));
                }
        }
        __syncthreads();
    }

    // store (each 8-wide n-tile all-or-nothing valid; N % 8 == 0 for all our shapes)
    #pragma unroll
    for (int mi = 0; mi < 2; mi++) {
        int row0 = bm * 128 + wm * 32 + mi * 16 + g;
        int row1 = row0 + 8;
        #pragma unroll
        for (int ni = 0; ni < 4; ni++) {
            int col = bn * 128 + wn * 32 + ni * 8 + tg * 2;
            if (col < N) {
                float2 v0 = make_float2(acc[mi][ni][0], acc[mi][ni][1]);
                float2 v1 = make_float2(acc[mi][ni][2], acc[mi][ni][3]);
                if (Res) {
                    float2 r0 = *(const float2*)(Res + (size_t)row0 * N + col);
                    float2 r1 = *(const float2*)(Res + (size_t)row1 * N + col);
                    v0.x += r0.x; v0.y += r0.y;
                    v1.x += r1.x; v1.y += r1.y;
                }
                *(float2*)(Cw + (size_t)row0 * N + col) = v0;
                *(float2*)(Cw + (size_t)row1 * N + col) = v1;
            }
        }
    }
}

// ---------------- silu(gate) * up, in place into gate ----------------
__global__ void act_k(float* __restrict__ g, const float* __restrict__ u, int n) {
    int idx = blockIdx.x * blockDim.x + threadIdx.x;
    if (idx >= n) return;
    float x = g[idx];
    g[idx] = siluf(x) * u[idx];
}

// ---------------- host launcher ----------------
extern "C" void kernel_launch(void* const* d_in, const int* in_sizes, int n_in,
                              void* d_out, int out_size) {
    const float* hid        = (const float*)d_in[0];
    const float* norm_w     = (const float*)d_in[1];
    const float* in_proj_w  = (const float*)d_in[2];
    const float* conv_w     = (const float*)d_in[3];
    const float* conv_b     = (const float*)d_in[4];
    const float* dt_bias    = (const float*)d_in[5];
    const float* A_log      = (const float*)d_in[6];
    const float* Dv         = (const float*)d_in[7];
    const float* ssm_norm_w = (const float*)d_in[8];
    const float* out_proj_w = (const float*)d_in[9];
    const float* post_norm_w= (const float*)d_in[10];
    const float* gate_w     = (const float*)d_in[11];
    const float* up_w       = (const float*)d_in[12];
    const float* down_w     = (const float*)d_in[13];
    float* out = (float*)d_out;

    float *p_xn, *p_zx, *p_cv, *p_y0, *p_y1, *p_y2, *p_y3, *p_yn, *p_x2, *p_hn,
          *p_gate, *p_up, *p_ps;
    cudaGetSymbolAddress((void**)&p_xn,   g_xn);
    cudaGetSymbolAddress((void**)&p_zx,   g_zx);
    cudaGetSymbolAddress((void**)&p_cv,   g_cv);
    cudaGetSymbolAddress((void**)&p_y0,   g_y0);
    cudaGetSymbolAddress((void**)&p_y1,   g_y1);
    cudaGetSymbolAddress((void**)&p_y2,   g_y2);
    cudaGetSymbolAddress((void**)&p_y3,   g_y3);
    cudaGetSymbolAddress((void**)&p_yn,   g_yn);
    cudaGetSymbolAddress((void**)&p_x2,   g_x2);
    cudaGetSymbolAddress((void**)&p_hn,   g_hn);
    cudaGetSymbolAddress((void**)&p_gate, g_gate);
    cudaGetSymbolAddress((void**)&p_up,   g_up);
    cudaGetSymbolAddress((void**)&p_ps,   g_ps);

    static int smem_set = 0;
    if (!smem_set) {
        cudaFuncSetAttribute(gemm_tf32, cudaFuncAttributeMaxDynamicSharedMemorySize,
                             GEMM_SMEM);
        smem_set = 1;
    }

    // 1. pre-norm
    rmsnorm1024_k<<<T_, 256>>>(hid, norm_w, p_xn);
    // 2. in_proj
    gemm_tf32<<<dim3(35, 16), 512, GEMM_SMEM>>>(p_xn, in_proj_w, in_proj_w, nullptr,
                                                p_zx, p_zx, T_, DPROJ, DM, NOSPLIT, 1, 0);
    // 3. conv + silu
    conv_k<<<(T_ * CONVD + 255) / 256, 256>>>(p_zx, conv_w, conv_b, p_cv);
    // 4. selective scan (4-way state split, partial outputs)
    scan_k<<<512, 256>>>(p_cv, p_zx, dt_bias, A_log, Dv, p_y0, p_y1, p_y2, p_y3);
    // 5. gated rmsnorm (sums partials)
    gated_norm_k<<<T_, 256>>>(p_y0, p_y1, p_y2, p_y3, p_zx, ssm_norm_w, p_yn);
    // 6. out_proj, split-K x3 (partials into g_ps)
    gemm_tf32<<<dim3(8, 16, 3), 512, GEMM_SMEM>>>(p_yn, out_proj_w, out_proj_w, nullptr,
                                                  p_ps, p_ps, T_, DM, DIN, NOSPLIT,
                                                  3, (size_t)T_ * DM);
    // 7. combine partials + residual, fused post-norm
    combine_norm_k<<<T_, 256>>>(p_ps, hid, post_norm_w, p_x2, p_hn);
    // 8. gate & up projections, fused into ONE launch (wave packing)
    gemm_tf32<<<dim3(44, 16), 512, GEMM_SMEM>>>(p_hn, gate_w, up_w, nullptr,
                                                p_gate, p_up, T_, INTER, DM, 22, 1, 0);
    // 9. silu(gate) * up
    act_k<<<(T_ * INTER + 255) / 256, 256>>>(p_gate, p_up, T_ * INTER);
    // 10. down projection, split-K x3
    gemm_tf32<<<dim3(8, 16, 3), 512, GEMM_SMEM>>>(p_gate, down_w, down_w, nullptr,
                                                  p_ps, p_ps, T_, DM, INTER, NOSPLIT,
                                                  3, (size_t)T_ * DM);
    // 11. final combine + residual -> output
    combine_k<<<T_ * DM / 1024, 256>>>(p_ps, p_x2, out);
}

// round 16
// speedup vs baseline: 1.0127x; 1.0127x over previous
#include <cuda_runtime.h>
#include <math.h>
#include <stdint.h>

// ---------------- problem constants ----------------
#define B_     2
#define L_     1024
#define T_     2048            // B_*L_
#define DM     1024            // d_model
#define DIN    2048            // d_inner
#define NH     32              // nheads
#define HD     64              // headdim
#define DS     128             // d_state
#define CONVD  2304            // DIN + 2*DS
#define DPROJ  4384            // 2*DIN + 2*DS + NH
#define INTER  2752
#define EPSF   1e-6f
#define TS     16              // scan time-chunk
#define NC     (L_/TS)         // 64 chunks (even)
#define NOSPLIT 0x40000000

#define GEMM_SMEM   (4 * 128 * 36 * 4)            // 2 stages x (As+Bs) 128x36 = 73728 B
#define GEMM64_SMEM ((2*64*36 + 2*128*36) * 4)    // m64 variant = 55296 B

// ---------------- scratch (device globals; no allocation allowed) ----------------
__device__ float g_xn  [(size_t)T_*DM];
__device__ float g_zx  [(size_t)T_*DPROJ];
__device__ float g_cv  [(size_t)T_*CONVD];
__device__ float g_y0  [(size_t)T_*DIN];
__device__ float g_y1  [(size_t)T_*DIN];
__device__ float g_y2  [(size_t)T_*DIN];
__device__ float g_y3  [(size_t)T_*DIN];
__device__ float g_yn  [(size_t)T_*DIN];
__device__ float g_x2  [(size_t)T_*DM];
__device__ float g_hn  [(size_t)T_*DM];
__device__ float g_gate[(size_t)T_*INTER];
__device__ float g_up  [(size_t)T_*INTER];

// ---------------- helpers ----------------
__device__ __forceinline__ float siluf(float x) {
    return x / (1.f + __expf(-x));
}

__device__ __forceinline__ uint32_t f2tf32(float x) {
    uint32_t r;
    asm("cvt.rna.tf32.f32 %0, %1;" : "=r"(r) : "f"(x));
    return r;
}

__device__ __forceinline__ uint32_t smem_u32(const void* p) {
    return (uint32_t)__cvta_generic_to_shared(p);
}

__device__ __forceinline__ void cp16(uint32_t dst, const void* src, int bytes) {
    asm volatile("cp.async.ca.shared.global [%0], [%1], 16, %2;"
                 :: "r"(dst), "l"(src), "r"(bytes));
}

__device__ __forceinline__ float block_reduce_sum(float v) {
    __shared__ float sh[32];
    int lane = threadIdx.x & 31, w = threadIdx.x >> 5;
    #pragma unroll
    for (int o = 16; o; o >>= 1) v += __shfl_xor_sync(0xffffffffu, v, o);
    if (lane == 0) sh[w] = v;
    __syncthreads();
    int nw = blockDim.x >> 5;
    v = (threadIdx.x < (unsigned)nw) ? sh[threadIdx.x] : 0.f;
    if (w == 0) {
        #pragma unroll
        for (int o = 16; o; o >>= 1) v += __shfl_xor_sync(0xffffffffu, v, o);
        if (lane == 0) sh[0] = v;
    }
    __syncthreads();
    return sh[0];
}

// ---------------- rmsnorm over D=1024 ----------------
__global__ void rmsnorm1024_k(const float* __restrict__ x, const float* __restrict__ w,
                              float* __restrict__ o) {
    int row = blockIdx.x;
    int i = threadIdx.x * 4;
    const float4 v = *(const float4*)(x + (size_t)row * DM + i);
    float ss = v.x*v.x + v.y*v.y + v.z*v.z + v.w*v.w;
    ss = block_reduce_sum(ss);
    float sc = rsqrtf(ss * (1.f / DM) + EPSF);
    float4 wv = *(const float4*)(w + i);
    float4 r;
    r.x = v.x * sc * wv.x; r.y = v.y * sc * wv.y;
    r.z = v.z * sc * wv.z; r.w = v.w * sc * wv.w;
    *(float4*)(o + (size_t)row * DM + i) = r;
}

// ---------- gated rmsnorm: out = rmsnorm((y0+y1+y2+y3) * silu(z)) * w ----------
__global__ void gated_norm_k(const float* __restrict__ y0, const float* __restrict__ y1,
                             const float* __restrict__ y2, const float* __restrict__ y3,
                             const float* __restrict__ zx,
                             const float* __restrict__ w, float* __restrict__ o) {
    int row = blockIdx.x;
    float vals[8];
    float ss = 0.f;
    #pragma unroll
    for (int c = 0; c < 2; c++) {
        int i = threadIdx.x * 4 + c * 1024;
        float4 ya = *(const float4*)(y0 + (size_t)row * DIN + i);
        float4 yb = *(const float4*)(y1 + (size_t)row * DIN + i);
        float4 yc = *(const float4*)(y2 + (size_t)row * DIN + i);
        float4 yd = *(const float4*)(y3 + (size_t)row * DIN + i);
        float4 zv = *(const float4*)(zx + (size_t)row * DPROJ + i);
        float a  = ((ya.x + yb.x) + (yc.x + yd.x)) * siluf(zv.x);
        float b  = ((ya.y + yb.y) + (yc.y + yd.y)) * siluf(zv.y);
        float cc = ((ya.z + yb.z) + (yc.z + yd.z)) * siluf(zv.z);
        float d  = ((ya.w + yb.w) + (yc.w + yd.w)) * siluf(zv.w);
        vals[c*4+0]=a; vals[c*4+1]=b; vals[c*4+2]=cc; vals[c*4+3]=d;
        ss += a*a + b*b + cc*cc + d*d;
    }
    ss = block_reduce_sum(ss);
    float sc = rsqrtf(ss * (1.f / DIN) + EPSF);
    #pragma unroll
    for (int c = 0; c < 2; c++) {
        int i = threadIdx.x * 4 + c * 1024;
        float4 wv = *(const float4*)(w + i);
        float4 r;
        r.x = vals[c*4+0] * sc * wv.x; r.y = vals[c*4+1] * sc * wv.y;
        r.z = vals[c*4+2] * sc * wv.z; r.w = vals[c*4+3] * sc * wv.w;
        *(float4*)(o + (size_t)row * DIN + i) = r;
    }
}

// ---------------- causal depthwise conv (width 4) + bias + silu ----------------
__global__ void conv_k(const float* __restrict__ zx, const float* __restrict__ w,
                       const float* __restrict__ bias, float* __restrict__ out) {
    int idx = blockIdx.x * blockDim.x + threadIdx.x;
    if (idx >= T_ * CONVD) return;
    int c   = idx % CONVD;
    int tok = idx / CONVD;
    int l   = tok % L_;
    const float* base = zx + (size_t)tok * DPROJ + DIN + c;
    float w0 = w[c*4+0], w1 = w[c*4+1], w2 = w[c*4+2], w3 = w[c*4+3];
    float acc = bias[c];
    if (l >= 3) acc += base[-(ptrdiff_t)3*DPROJ] * w0;
    if (l >= 2) acc += base[-(ptrdiff_t)2*DPROJ] * w1;
    if (l >= 1) acc += base[-(ptrdiff_t)1*DPROJ] * w2;
    acc += base[0] * w3;
    out[idx] = siluf(acc);
}

// ---------------- selective scan: 4-way state split, 512 blocks (R11 WIN) ----------
__global__ void __launch_bounds__(256) scan_k(const float* __restrict__ cv,
                                              const float* __restrict__ zx,
                                              const float* __restrict__ dt_bias,
                                              const float* __restrict__ A_log,
                                              const float* __restrict__ Dv,
                                              float* __restrict__ yA,
                                              float* __restrict__ yB,
                                              float* __restrict__ yC,
                                              float* __restrict__ yD) {
    int bid = blockIdx.x;
    int ns  = bid & 3;
    int ps  = (bid >> 2) & 1;
    int h   = (bid >> 3) & 31;
    int b   = bid >> 8;
    int tid = threadIdx.x;
    int pl  = tid >> 3;          // 0..31
    int nl  = tid & 7;           // 0..7
    int nb  = nl * 4;            // state offset within 32-slice

    __shared__ float sDt[L_];
    __shared__ float sDA[L_];
    __shared__ float sB0[TS][36], sB1[TS][36];
    __shared__ float sC0[TS][36], sC1[TS][36];
    __shared__ float sX0[TS][32], sX1[TS][32];

    float Ah   = -__expf(A_log[h]);
    float Dh   = Dv[h];
    float bias = dt_bias[h];

    {
        const float* dptr = zx + (size_t)b * L_ * DPROJ + (DPROJ - NH) + h;
        for (int t = tid; t < L_; t += 256) {
            float v  = dptr[(size_t)t * DPROJ] + bias;
            float dt = (v > 20.f) ? v : log1pf(__expf(v));
            sDt[t] = dt;
            sDA[t] = __expf(dt * Ah);
        }
    }

    const float* bcbase = cv + (size_t)b * L_ * CONVD + DIN + ns * 32;  // B slice; C at +DS
    const float* xbase  = cv + (size_t)b * L_ * CONVD + h * HD + ps * 32;

    auto stage = [&](int c, float (*SB)[36], float (*SC)[36], float (*SX)[32]) {
        int t0 = c * TS;
        {   // B|C: 16 tokens x (8+8) float4 = 256 loads, one per thread
            int t = tid >> 4;
            int j = tid & 15;
            const float* src = bcbase + (size_t)(t0 + t) * CONVD
                             + ((j < 8) ? (j * 4) : (DS + (j - 8) * 4));
            float4 v = *(const float4*)src;
            if (j < 8) *(float4*)&SB[t][j * 4] = v;
            else       *(float4*)&SC[t][(j - 8) * 4] = v;
        }
        if (tid < 128) {         // X: 16 tokens x 8 float4
            int t = tid >> 3, j = tid & 7;
            *(float4*)&SX[t][j * 4] =
                *(const float4*)(xbase + (size_t)(t0 + t) * CONVD + j * 4);
        }
    };

    float hs[4];
    #pragma unroll
    for (int i = 0; i < 4; i++) hs[i] = 0.f;

    float* ypart = (ns == 0) ? yA : ((ns == 1) ? yB : ((ns == 2) ? yC : yD));
    float* yptr  = ypart + (size_t)b * L_ * DIN + h * HD + ps * 32 + pl;
    bool writer  = (nl == 0);
    float Dterm  = (ns == 0) ? Dh : 0.f;

    auto compute = [&](int c, float (*SB)[36], float (*SC)[36], float (*SX)[32]) {
        #pragma unroll
        for (int tt = 0; tt < TS; tt++) {
            int t = c * TS + tt;
            float dt  = sDt[t];
            float dA  = sDA[t];
            float xv  = SX[tt][pl];
            float dtx = dt * xv;

            float4 bb = *(const float4*)&SB[tt][nb];
            float4 cc = *(const float4*)&SC[tt][nb];

            float yp0 = 0.f, yp1 = 0.f;
            hs[0] = fmaf(hs[0], dA, dtx * bb.x); yp0 = fmaf(hs[0], cc.x, yp0);
            hs[1] = fmaf(hs[1], dA, dtx * bb.y); yp1 = fmaf(hs[1], cc.y, yp1);
            hs[2] = fmaf(hs[2], dA, dtx * bb.z); yp0 = fmaf(hs[2], cc.z, yp0);
            hs[3] = fmaf(hs[3], dA, dtx * bb.w); yp1 = fmaf(hs[3], cc.w, yp1);

            float yp = yp0 + yp1;
            yp += __shfl_xor_sync(0xffffffffu, yp, 1);
            yp += __shfl_xor_sync(0xffffffffu, yp, 2);
            yp += __shfl_xor_sync(0xffffffffu, yp, 4);
            if (writer)
                yptr[(size_t)t * DIN] = yp + Dterm * xv;
        }
    };

    stage(0, sB0, sC0, sX0);
    __syncthreads();

    for (int c = 0; c < NC; c += 2) {
        stage(c + 1, sB1, sC1, sX1);
        compute(c, sB0, sC0, sX0);
        __syncthreads();
        if (c + 2 < NC) stage(c + 2, sB0, sC0, sX0);
        compute(c + 1, sB1, sC1, sX1);
        __syncthreads();
    }
}

// ---------------- tf32 tensor-core GEMM, cp.async 2-stage, 512 threads ------------
// C[M,N] = A[M,K] * B[N,K]^T (+ Res). 128x128 block tile, BK=32,
// 16 warps (4x4), warp tile 32x32, mma.sync.m16n8k8 tf32.
// Dual-output fusion via nsplit (blockIdx.x >= nsplit -> Bm2/C2).
__global__ void __launch_bounds__(512) gemm_tf32(const float* __restrict__ A,
                                                 const float* __restrict__ Bm,
                                                 const float* __restrict__ Bm2,
                                                 const float* __restrict__ Res,
                                                 float* __restrict__ C,
                                                 float* __restrict__ C2,
                                                 int M, int N, int K, int nsplit) {
    extern __shared__ float dsm[];
    float* AsBase = dsm;                       // [2][128][36]
    float* BsBase = dsm + 2 * 128 * 36;        // [2][128][36]

    int tid  = threadIdx.x;
    int bm   = blockIdx.y;
    int bn   = blockIdx.x;
    const float* Bw = Bm;
    float* Cw = C;
    if (bn >= nsplit) { bn -= nsplit; Bw = Bm2; Cw = C2; }

    int wid  = tid >> 5;
    int lane = tid & 31;
    int wm   = wid >> 2;         // 0..3
    int wn   = wid & 3;          // 0..3
    int g    = lane >> 2;        // 0..7
    int tg   = lane & 3;         // 0..3

    int srow = tid >> 2;               // 0..127 (4 threads per row)
    int sc4  = (tid & 3) * 2;          // first float4 index (0,2,4,6)

    const float* Aab = A + (size_t)(bm * 128 + srow) * K + sc4 * 4;
    int nrow = bn * 128 + srow;
    const float* Bab = Bw + (size_t)nrow * K + sc4 * 4;
    int nvbytes = (nrow < N) ? 16 : 0;

    float acc[2][4][4];
    #pragma unroll
    for (int mi = 0; mi < 2; mi++)
        #pragma unroll
        for (int ni = 0; ni < 4; ni++)
            #pragma unroll
            for (int r = 0; r < 4; r++) acc[mi][ni][r] = 0.f;

    int nk = K >> 5;

    float* Asw = AsBase + (size_t)srow * 36 + sc4 * 4;   // + buf*128*36
    float* Bsw = BsBase + (size_t)srow * 36 + sc4 * 4;

    auto stage = [&](int kt, int buf) {
        const float* a = Aab + (size_t)kt * 32;
        const float* b = Bab + (size_t)kt * 32;
        float* ad = Asw + (size_t)buf * 128 * 36;
        float* bd = Bsw + (size_t)buf * 128 * 36;
        #pragma unroll
        for (int q = 0; q < 2; q++) {
            cp16(smem_u32(ad + q * 4), a + q * 4, 16);
            cp16(smem_u32(bd + q * 4), b + q * 4, nvbytes);
        }
        asm volatile("cp.async.commit_group;" ::: "memory");
    };

    stage(0, 0);

    for (int kt = 0; kt < nk; kt++) {
        int buf = kt & 1;
        asm volatile("cp.async.wait_group 0;" ::: "memory");
        __syncthreads();
        if (kt + 1 < nk) stage(kt + 1, buf ^ 1);

        const float (*AsT)[36] = (const float(*)[36])(AsBase + (size_t)buf * 128 * 36);
        const float (*BsT)[36] = (const float(*)[36])(BsBase + (size_t)buf * 128 * 36);

        #pragma unroll
        for (int ks = 0; ks < 4; ks++) {
            int kk = ks * 8;
            uint32_t af[2][4];
            #pragma unroll
            for (int mi = 0; mi < 2; mi++) {
                int m0 = wm * 32 + mi * 16;
                af[mi][0] = f2tf32(AsT[m0 + g    ][kk + tg    ]);
                af[mi][1] = f2tf32(AsT[m0 + g + 8][kk + tg    ]);
                af[mi][2] = f2tf32(AsT[m0 + g    ][kk + tg + 4]);
                af[mi][3] = f2tf32(AsT[m0 + g + 8][kk + tg + 4]);
            }
            uint32_t bf[4][2];
            #pragma unroll
            for (int ni = 0; ni < 4; ni++) {
                int n0 = wn * 32 + ni * 8;
                bf[ni][0] = f2tf32(BsT[n0 + g][kk + tg    ]);
                bf[ni][1] = f2tf32(BsT[n0 + g][kk + tg + 4]);
            }
            #pragma unroll
            for (int mi = 0; mi < 2; mi++)
                #pragma unroll
                for (int ni = 0; ni < 4; ni++) {
                    asm volatile(
                        "mma.sync.aligned.m16n8k8.row.col.f32.tf32.tf32.f32 "
                        "{%0,%1,%2,%3}, {%4,%5,%6,%7}, {%8,%9}, {%0,%1,%2,%3};"
                        : "+f"(acc[mi][ni][0]), "+f"(acc[mi][ni][1]),
                          "+f"(acc[mi][ni][2]), "+f"(acc[mi][ni][3])
                        : "r"(af[mi][0]), "r"(af[mi][1]), "r"(af[mi][2]), "r"(af[mi][3]),
                          "r"(bf[ni][0]), "r"(bf[ni][1]));
                }
        }
        __syncthreads();
    }

    #pragma unroll
    for (int mi = 0; mi < 2; mi++) {
        int row0 = bm * 128 + wm * 32 + mi * 16 + g;
        int row1 = row0 + 8;
        #pragma unroll
        for (int ni = 0; ni < 4; ni++) {
            int col = bn * 128 + wn * 32 + ni * 8 + tg * 2;
            if (col < N) {
                float2 v0 = make_float2(acc[mi][ni][0], acc[mi][ni][1]);
                float2 v1 = make_float2(acc[mi][ni][2], acc[mi][ni][3]);
                if (Res) {
                    float2 r0 = *(const float2*)(Res + (size_t)row0 * N + col);
                    float2 r1 = *(const float2*)(Res + (size_t)row1 * N + col);
                    v0.x += r0.x; v0.y += r0.y;
                    v1.x += r1.x; v1.y += r1.y;
                }
                *(float2*)(Cw + (size_t)row0 * N + col) = v0;
                *(float2*)(Cw + (size_t)row1 * N + col) = v1;
            }
        }
    }
}

// -------- m64 variant: 64x128 block tile (2x the blocks for small GEMMs) --------
// 16 warps (2x8), warp tile 32x16. A smem [2][64][36], B smem [2][128][36].
// N must be a multiple of 128 here (used for N=1024 only).
__global__ void __launch_bounds__(512) gemm_tf32_m64(const float* __restrict__ A,
                                                     const float* __restrict__ Bm,
                                                     const float* __restrict__ Res,
                                                     float* __restrict__ C,
                                                     int M, int N, int K) {
    extern __shared__ float dsm[];
    float* AsBase = dsm;                       // [2][64][36]
    float* BsBase = dsm + 2 * 64 * 36;         // [2][128][36]

    int tid  = threadIdx.x;
    int bm   = blockIdx.y;
    int bn   = blockIdx.x;

    int wid  = tid >> 5;
    int lane = tid & 31;
    int wm   = wid >> 3;         // 0..1
    int wn   = wid & 7;          // 0..7
    int g    = lane >> 2;        // 0..7
    int tg   = lane & 3;         // 0..3

    // A staging: 64 rows x 8 float4 = 512 -> 1 per thread
    int arow = tid >> 3;               // 0..63
    int ac4  = tid & 7;                // 0..7
    // B staging: 128 rows x 8 float4 = 1024 -> 2 per thread (contiguous pair)
    int brow = tid >> 2;               // 0..127
    int bc4  = (tid & 3) * 2;          // first float4 index: 0,2,4,6

    const float* Aab = A + (size_t)(bm * 64 + arow) * K + ac4 * 4;
    const float* Bab = Bm + (size_t)(bn * 128 + brow) * K + bc4 * 4;

    float acc[2][2][4];
    #pragma unroll
    for (int mi = 0; mi < 2; mi++)
        #pragma unroll
        for (int ni = 0; ni < 2; ni++)
            #pragma unroll
            for (int r = 0; r < 4; r++) acc[mi][ni][r] = 0.f;

    int nk = K >> 5;

    float* Asw = AsBase + (size_t)arow * 36 + ac4 * 4;
    float* Bsw = BsBase + (size_t)brow * 36 + bc4 * 4;

    auto stage = [&](int kt, int buf) {
        const float* a = Aab + (size_t)kt * 32;
        const float* b = Bab + (size_t)kt * 32;
        cp16(smem_u32(Asw + (size_t)buf * 64 * 36), a, 16);
        float* bd = Bsw + (size_t)buf * 128 * 36;
        cp16(smem_u32(bd),     b,     16);     // float4 index bc4
        cp16(smem_u32(bd + 4), b + 4, 16);     // float4 index bc4+1
        asm volatile("cp.async.commit_group;" ::: "memory");
    };

    stage(0, 0);

    for (int kt = 0; kt < nk; kt++) {
        int buf = kt & 1;
        asm volatile("cp.async.wait_group 0;" ::: "memory");
        __syncthreads();
        if (kt + 1 < nk) stage(kt + 1, buf ^ 1);

        const float (*AsT)[36] = (const float(*)[36])(AsBase + (size_t)buf * 64 * 36);
        const float (*BsT)[36] = (const float(*)[36])(BsBase + (size_t)buf * 128 * 36);

        #pragma unroll
        for (int ks = 0; ks < 4; ks++) {
            int kk = ks * 8;
            uint32_t af[2][4];
            #pragma unroll
            for (int mi = 0; mi < 2; mi++) {
                int m0 = wm * 32 + mi * 16;
                af[mi][0] = f2tf32(AsT[m0 + g    ][kk + tg    ]);
                af[mi][1] = f2tf32(AsT[m0 + g + 8][kk + tg    ]);
                af[mi][2] = f2tf32(AsT[m0 + g    ][kk + tg + 4]);
                af[mi][3] = f2tf32(AsT[m0 + g + 8][kk + tg + 4]);
            }
            uint32_t bf[2][2];
            #pragma unroll
            for (int ni = 0; ni < 2; ni++) {
                int n0 = wn * 16 + ni * 8;
                bf[ni][0] = f2tf32(BsT[n0 + g][kk + tg    ]);
                bf[ni][1] = f2tf32(BsT[n0 + g][kk + tg + 4]);
            }
            #pragma unroll
            for (int mi = 0; mi < 2; mi++)
                #pragma unroll
                for (int ni = 0; ni < 2; ni++) {
                    asm volatile(
                        "mma.sync.aligned.m16n8k8.row.col.f32.tf32.tf32.f32 "
                        "{%0,%1,%2,%3}, {%4,%5,%6,%7}, {%8,%9}, {%0,%1,%2,%3};"
                        : "+f"(acc[mi][ni][0]), "+f"(acc[mi][ni][1]),
                          "+f"(acc[mi][ni][2]), "+f"(acc[mi][ni][3])
                        : "r"(af[mi][0]), "r"(af[mi][1]), "r"(af[mi][2]), "r"(af[mi][3]),
                          "r"(bf[ni][0]), "r"(bf[ni][1]));
                }
        }
        __syncthreads();
    }

    #pragma unroll
    for (int mi = 0; mi < 2; mi++) {
        int row0 = bm * 64 + wm * 32 + mi * 16 + g;
        int row1 = row0 + 8;
        #pragma unroll
        for (int ni = 0; ni < 2; ni++) {
            int col = bn * 128 + wn * 16 + ni * 8 + tg * 2;
            float2 v0 = make_float2(acc[mi][ni][0], acc[mi][ni][1]);
            float2 v1 = make_float2(acc[mi][ni][2], acc[mi][ni][3]);
            if (Res) {
                float2 r0 = *(const float2*)(Res + (size_t)row0 * N + col);
                float2 r1 = *(const float2*)(Res + (size_t)row1 * N + col);
                v0.x += r0.x; v0.y += r0.y;
                v1.x += r1.x; v1.y += r1.y;
            }
            *(float2*)(C + (size_t)row0 * N + col) = v0;
            *(float2*)(C + (size_t)row1 * N + col) = v1;
        }
    }
}

// ---------------- silu(gate) * up, in place into gate ----------------
__global__ void act_k(float* __restrict__ g, const float* __restrict__ u, int n) {
    int idx = blockIdx.x * blockDim.x + threadIdx.x;
    if (idx >= n) return;
    float x = g[idx];
    g[idx] = siluf(x) * u[idx];
}

// ---------------- host launcher ----------------
extern "C" void kernel_launch(void* const* d_in, const int* in_sizes, int n_in,
                              void* d_out, int out_size) {
    const float* hid        = (const float*)d_in[0];
    const float* norm_w     = (const float*)d_in[1];
    const float* in_proj_w  = (const float*)d_in[2];
    const float* conv_w     = (const float*)d_in[3];
    const float* conv_b     = (const float*)d_in[4];
    const float* dt_bias    = (const float*)d_in[5];
    const float* A_log      = (const float*)d_in[6];
    const float* Dv         = (const float*)d_in[7];
    const float* ssm_norm_w = (const float*)d_in[8];
    const float* out_proj_w = (const float*)d_in[9];
    const float* post_norm_w= (const float*)d_in[10];
    const float* gate_w     = (const float*)d_in[11];
    const float* up_w       = (const float*)d_in[12];
    const float* down_w     = (const float*)d_in[13];
    float* out = (float*)d_out;

    float *p_xn, *p_zx, *p_cv, *p_y0, *p_y1, *p_y2, *p_y3, *p_yn, *p_x2, *p_hn,
          *p_gate, *p_up;
    cudaGetSymbolAddress((void**)&p_xn,   g_xn);
    cudaGetSymbolAddress((void**)&p_zx,   g_zx);
    cudaGetSymbolAddress((void**)&p_cv,   g_cv);
    cudaGetSymbolAddress((void**)&p_y0,   g_y0);
    cudaGetSymbolAddress((void**)&p_y1,   g_y1);
    cudaGetSymbolAddress((void**)&p_y2,   g_y2);
    cudaGetSymbolAddress((void**)&p_y3,   g_y3);
    cudaGetSymbolAddress((void**)&p_yn,   g_yn);
    cudaGetSymbolAddress((void**)&p_x2,   g_x2);
    cudaGetSymbolAddress((void**)&p_hn,   g_hn);
    cudaGetSymbolAddress((void**)&p_gate, g_gate);
    cudaGetSymbolAddress((void**)&p_up,   g_up);

    static int smem_set = 0;
    if (!smem_set) {
        cudaFuncSetAttribute(gemm_tf32, cudaFuncAttributeMaxDynamicSharedMemorySize,
                             GEMM_SMEM);
        cudaFuncSetAttribute(gemm_tf32_m64, cudaFuncAttributeMaxDynamicSharedMemorySize,
                             GEMM64_SMEM);
        smem_set = 1;
    }

    // 1. pre-norm
    rmsnorm1024_k<<<T_, 256>>>(hid, norm_w, p_xn);
    // 2. in_proj
    gemm_tf32<<<dim3(35, 16), 512, GEMM_SMEM>>>(p_xn, in_proj_w, in_proj_w, nullptr,
                                                p_zx, p_zx, T_, DPROJ, DM, NOSPLIT);
    // 3. conv + silu
    conv_k<<<(T_ * CONVD + 255) / 256, 256>>>(p_zx, conv_w, conv_b, p_cv);
    // 4. selective scan (4-way state split, partial outputs)
    scan_k<<<512, 256>>>(p_cv, p_zx, dt_bias, A_log, Dv, p_y0, p_y1, p_y2, p_y3);
    // 5. gated rmsnorm (sums partials)
    gated_norm_k<<<T_, 256>>>(p_y0, p_y1, p_y2, p_y3, p_zx, ssm_norm_w, p_yn);
    // 6. out_proj + residual (m64 tiles: 256 blocks)
    gemm_tf32_m64<<<dim3(8, 32), 512, GEMM64_SMEM>>>(p_yn, out_proj_w, hid,
                                                     p_x2, T_, DM, DIN);
    // 7. post-norm
    rmsnorm1024_k<<<T_, 256>>>(p_x2, post_norm_w, p_hn);
    // 8. gate & up projections, fused into ONE launch (wave packing)
    gemm_tf32<<<dim3(44, 16), 512, GEMM_SMEM>>>(p_hn, gate_w, up_w, nullptr,
                                                p_gate, p_up, T_, INTER, DM, 22);
    // 9. silu(gate) * up
    act_k<<<(T_ * INTER + 255) / 256, 256>>>(p_gate, p_up, T_ * INTER);
    // 10. down projection + residual -> output (m64 tiles: 256 blocks)
    gemm_tf32_m64<<<dim3(8, 32), 512, GEMM64_SMEM>>>(p_gate, down_w, p_x2,
                                                     out, T_, DM, INTER);
}

// round 17
// speedup vs baseline: 1.0730x; 1.0595x over previous
#include <cuda_runtime.h>
#include <math.h>
#include <stdint.h>

// ---------------- problem constants ----------------
#define B_     2
#define L_     1024
#define T_     2048            // B_*L_
#define DM     1024            // d_model
#define DIN    2048            // d_inner
#define NH     32              // nheads
#define HD     64              // headdim
#define DS     128             // d_state
#define CONVD  2304            // DIN + 2*DS
#define DPROJ  4384            // 2*DIN + 2*DS + NH
#define INTER  2752
#define EPSF   1e-6f
#define TS     16              // scan time-chunk
#define NC     (L_/TS)         // 64 chunks (even)
#define NOSPLIT 0x40000000

#define GEMM_SMEM (4 * 128 * 36 * 4)   // 2 stages x (As+Bs) x 128x36 floats = 73728 B

// ---------------- scratch (device globals; no allocation allowed) ----------------
__device__ float g_xn  [(size_t)T_*DM];
__device__ float g_zx  [(size_t)T_*DPROJ];
__device__ float g_cv  [(size_t)T_*CONVD];
__device__ float g_y0  [(size_t)T_*DIN];
__device__ float g_y1  [(size_t)T_*DIN];
__device__ float g_y2  [(size_t)T_*DIN];
__device__ float g_y3  [(size_t)T_*DIN];
__device__ float g_yn  [(size_t)T_*DIN];
__device__ float g_x2  [(size_t)T_*DM];
__device__ float g_hn  [(size_t)T_*DM];
__device__ float g_gate[(size_t)T_*INTER];
__device__ float g_up  [(size_t)T_*INTER];

// ---------------- helpers ----------------
__device__ __forceinline__ float siluf(float x) {
    return x / (1.f + __expf(-x));
}

__device__ __forceinline__ uint32_t f2tf32(float x) {
    uint32_t r;
    asm("cvt.rna.tf32.f32 %0, %1;" : "=r"(r) : "f"(x));
    return r;
}

__device__ __forceinline__ uint32_t smem_u32(const void* p) {
    return (uint32_t)__cvta_generic_to_shared(p);
}

__device__ __forceinline__ void cp16(uint32_t dst, const void* src, int bytes) {
    asm volatile("cp.async.ca.shared.global [%0], [%1], 16, %2;"
                 :: "r"(dst), "l"(src), "r"(bytes));
}

__device__ __forceinline__ float block_reduce_sum(float v) {
    __shared__ float sh[32];
    int lane = threadIdx.x & 31, w = threadIdx.x >> 5;
    #pragma unroll
    for (int o = 16; o; o >>= 1) v += __shfl_xor_sync(0xffffffffu, v, o);
    if (lane == 0) sh[w] = v;
    __syncthreads();
    int nw = blockDim.x >> 5;
    v = (threadIdx.x < (unsigned)nw) ? sh[threadIdx.x] : 0.f;
    if (w == 0) {
        #pragma unroll
        for (int o = 16; o; o >>= 1) v += __shfl_xor_sync(0xffffffffu, v, o);
        if (lane == 0) sh[0] = v;
    }
    __syncthreads();
    return sh[0];
}

// ---------------- rmsnorm over D=1024 ----------------
__global__ void rmsnorm1024_k(const float* __restrict__ x, const float* __restrict__ w,
                              float* __restrict__ o) {
    int row = blockIdx.x;
    int i = threadIdx.x * 4;
    const float4 v = *(const float4*)(x + (size_t)row * DM + i);
    float ss = v.x*v.x + v.y*v.y + v.z*v.z + v.w*v.w;
    ss = block_reduce_sum(ss);
    float sc = rsqrtf(ss * (1.f / DM) + EPSF);
    float4 wv = *(const float4*)(w + i);
    float4 r;
    r.x = v.x * sc * wv.x; r.y = v.y * sc * wv.y;
    r.z = v.z * sc * wv.z; r.w = v.w * sc * wv.w;
    *(float4*)(o + (size_t)row * DM + i) = r;
}

// ---------- gated rmsnorm: out = rmsnorm((y0+y1+y2+y3) * silu(z)) * w ----------
__global__ void gated_norm_k(const float* __restrict__ y0, const float* __restrict__ y1,
                             const float* __restrict__ y2, const float* __restrict__ y3,
                             const float* __restrict__ zx,
                             const float* __restrict__ w, float* __restrict__ o) {
    int row = blockIdx.x;
    float vals[8];
    float ss = 0.f;
    #pragma unroll
    for (int c = 0; c < 2; c++) {
        int i = threadIdx.x * 4 + c * 1024;
        float4 ya = *(const float4*)(y0 + (size_t)row * DIN + i);
        float4 yb = *(const float4*)(y1 + (size_t)row * DIN + i);
        float4 yc = *(const float4*)(y2 + (size_t)row * DIN + i);
        float4 yd = *(const float4*)(y3 + (size_t)row * DIN + i);
        float4 zv = *(const float4*)(zx + (size_t)row * DPROJ + i);
        float a  = ((ya.x + yb.x) + (yc.x + yd.x)) * siluf(zv.x);
        float b  = ((ya.y + yb.y) + (yc.y + yd.y)) * siluf(zv.y);
        float cc = ((ya.z + yb.z) + (yc.z + yd.z)) * siluf(zv.z);
        float d  = ((ya.w + yb.w) + (yc.w + yd.w)) * siluf(zv.w);
        vals[c*4+0]=a; vals[c*4+1]=b; vals[c*4+2]=cc; vals[c*4+3]=d;
        ss += a*a + b*b + cc*cc + d*d;
    }
    ss = block_reduce_sum(ss);
    float sc = rsqrtf(ss * (1.f / DIN) + EPSF);
    #pragma unroll
    for (int c = 0; c < 2; c++) {
        int i = threadIdx.x * 4 + c * 1024;
        float4 wv = *(const float4*)(w + i);
        float4 r;
        r.x = vals[c*4+0] * sc * wv.x; r.y = vals[c*4+1] * sc * wv.y;
        r.z = vals[c*4+2] * sc * wv.z; r.w = vals[c*4+3] * sc * wv.w;
        *(float4*)(o + (size_t)row * DIN + i) = r;
    }
}

// ---------------- causal depthwise conv (width 4) + bias + silu ----------------
__global__ void conv_k(const float* __restrict__ zx, const float* __restrict__ w,
                       const float* __restrict__ bias, float* __restrict__ out) {
    int idx = blockIdx.x * blockDim.x + threadIdx.x;
    if (idx >= T_ * CONVD) return;
    int c   = idx % CONVD;
    int tok = idx / CONVD;
    int l   = tok % L_;
    const float* base = zx + (size_t)tok * DPROJ + DIN + c;
    float w0 = w[c*4+0], w1 = w[c*4+1], w2 = w[c*4+2], w3 = w[c*4+3];
    float acc = bias[c];
    if (l >= 3) acc += base[-(ptrdiff_t)3*DPROJ] * w0;
    if (l >= 2) acc += base[-(ptrdiff_t)2*DPROJ] * w1;
    if (l >= 1) acc += base[-(ptrdiff_t)1*DPROJ] * w2;
    acc += base[0] * w3;
    out[idx] = siluf(acc);
}

// ---------------- selective scan: 4-way state split, 512 blocks ----------------
// bid -> ns(4: 32-state slice) x ps(2: p-half) x h(32) x b(2). 256 threads.
// thread: pl = tid>>3 (0..31), nl = tid&7 -> 4 states at ns*32 + nl*4. hs[4].
// dt/dA packed as float2 -> one LDS.64 instead of two LDS.32 per step.
__global__ void __launch_bounds__(256) scan_k(const float* __restrict__ cv,
                                              const float* __restrict__ zx,
                                              const float* __restrict__ dt_bias,
                                              const float* __restrict__ A_log,
                                              const float* __restrict__ Dv,
                                              float* __restrict__ yA,
                                              float* __restrict__ yB,
                                              float* __restrict__ yC,
                                              float* __restrict__ yD) {
    int bid = blockIdx.x;
    int ns  = bid & 3;
    int ps  = (bid >> 2) & 1;
    int h   = (bid >> 3) & 31;
    int b   = bid >> 8;
    int tid = threadIdx.x;
    int pl  = tid >> 3;          // 0..31
    int nl  = tid & 7;           // 0..7
    int nb  = nl * 4;            // state offset within 32-slice

    __shared__ float2 sDtA[L_];          // (dt, dA) packed
    __shared__ float sB0[TS][36], sB1[TS][36];
    __shared__ float sC0[TS][36], sC1[TS][36];
    __shared__ float sX0[TS][32], sX1[TS][32];

    float Ah   = -__expf(A_log[h]);
    float Dh   = Dv[h];
    float bias = dt_bias[h];

    {
        const float* dptr = zx + (size_t)b * L_ * DPROJ + (DPROJ - NH) + h;
        for (int t = tid; t < L_; t += 256) {
            float v  = dptr[(size_t)t * DPROJ] + bias;
            float dt = (v > 20.f) ? v : log1pf(__expf(v));
            sDtA[t] = make_float2(dt, __expf(dt * Ah));
        }
    }

    const float* bcbase = cv + (size_t)b * L_ * CONVD + DIN + ns * 32;  // B slice; C at +DS
    const float* xbase  = cv + (size_t)b * L_ * CONVD + h * HD + ps * 32;

    auto stage = [&](int c, float (*SB)[36], float (*SC)[36], float (*SX)[32]) {
        int t0 = c * TS;
        {   // B|C: 16 tokens x (8+8) float4 = 256 loads, one per thread
            int t = tid >> 4;
            int j = tid & 15;
            const float* src = bcbase + (size_t)(t0 + t) * CONVD
                             + ((j < 8) ? (j * 4) : (DS + (j - 8) * 4));
            float4 v = *(const float4*)src;
            if (j < 8) *(float4*)&SB[t][j * 4] = v;
            else       *(float4*)&SC[t][(j - 8) * 4] = v;
        }
        if (tid < 128) {         // X: 16 tokens x 8 float4
            int t = tid >> 3, j = tid & 7;
            *(float4*)&SX[t][j * 4] =
                *(const float4*)(xbase + (size_t)(t0 + t) * CONVD + j * 4);
        }
    };

    float hs[4];
    #pragma unroll
    for (int i = 0; i < 4; i++) hs[i] = 0.f;

    float* ypart = (ns == 0) ? yA : ((ns == 1) ? yB : ((ns == 2) ? yC : yD));
    float* yptr  = ypart + (size_t)b * L_ * DIN + h * HD + ps * 32 + pl;
    bool writer  = (nl == 0);
    float Dterm  = (ns == 0) ? Dh : 0.f;

    auto compute = [&](int c, float (*SB)[36], float (*SC)[36], float (*SX)[32]) {
        #pragma unroll
        for (int tt = 0; tt < TS; tt++) {
            int t = c * TS + tt;
            float2 dd = sDtA[t];
            float dt  = dd.x;
            float dA  = dd.y;
            float xv  = SX[tt][pl];
            float dtx = dt * xv;

            float4 bb = *(const float4*)&SB[tt][nb];
            float4 cc = *(const float4*)&SC[tt][nb];

            float yp0 = 0.f, yp1 = 0.f;
            hs[0] = fmaf(hs[0], dA, dtx * bb.x); yp0 = fmaf(hs[0], cc.x, yp0);
            hs[1] = fmaf(hs[1], dA, dtx * bb.y); yp1 = fmaf(hs[1], cc.y, yp1);
            hs[2] = fmaf(hs[2], dA, dtx * bb.z); yp0 = fmaf(hs[2], cc.z, yp0);
            hs[3] = fmaf(hs[3], dA, dtx * bb.w); yp1 = fmaf(hs[3], cc.w, yp1);

            float yp = yp0 + yp1;
            yp += __shfl_xor_sync(0xffffffffu, yp, 1);
            yp += __shfl_xor_sync(0xffffffffu, yp, 2);
            yp += __shfl_xor_sync(0xffffffffu, yp, 4);
            if (writer)
                yptr[(size_t)t * DIN] = yp + Dterm * xv;
        }
    };

    stage(0, sB0, sC0, sX0);
    __syncthreads();

    for (int c = 0; c < NC; c += 2) {
        stage(c + 1, sB1, sC1, sX1);
        compute(c, sB0, sC0, sX0);
        __syncthreads();
        if (c + 2 < NC) stage(c + 2, sB0, sC0, sX0);
        compute(c + 1, sB1, sC1, sX1);
        __syncthreads();
    }
}

// ---------------- tf32 tensor-core GEMM, cp.async 2-stage, 512 threads ------------
// C[M,N] = A[M,K] * B[N,K]^T (+ Res). 128x128 block tile, BK=32,
// 16 warps (4x4), warp tile 32x32, mma.sync.m16n8k8 tf32.
// Dual-output fusion via nsplit (blockIdx.x >= nsplit -> Bm2/C2).
__global__ void __launch_bounds__(512) gemm_tf32(const float* __restrict__ A,
                                                 const float* __restrict__ Bm,
                                                 const float* __restrict__ Bm2,
                                                 const float* __restrict__ Res,
                                                 float* __restrict__ C,
                                                 float* __restrict__ C2,
                                                 int M, int N, int K, int nsplit) {
    extern __shared__ float dsm[];
    float* AsBase = dsm;                       // [2][128][36]
    float* BsBase = dsm + 2 * 128 * 36;        // [2][128][36]

    int tid  = threadIdx.x;
    int bm   = blockIdx.y;
    int bn   = blockIdx.x;
    const float* Bw = Bm;
    float* Cw = C;
    if (bn >= nsplit) { bn -= nsplit; Bw = Bm2; Cw = C2; }

    int wid  = tid >> 5;
    int lane = tid & 31;
    int wm   = wid >> 2;         // 0..3
    int wn   = wid & 3;          // 0..3
    int g    = lane >> 2;        // 0..7
    int tg   = lane & 3;         // 0..3

    int srow = tid >> 2;               // 0..127 (4 threads per row)
    int sc4  = (tid & 3) * 2;          // first float4 index (0,2,4,6)

    const float* Aab = A + (size_t)(bm * 128 + srow) * K + sc4 * 4;
    int nrow = bn * 128 + srow;
    const float* Bab = Bw + (size_t)nrow * K + sc4 * 4;
    int nvbytes = (nrow < N) ? 16 : 0;

    float acc[2][4][4];
    #pragma unroll
    for (int mi = 0; mi < 2; mi++)
        #pragma unroll
        for (int ni = 0; ni < 4; ni++)
            #pragma unroll
            for (int r = 0; r < 4; r++) acc[mi][ni][r] = 0.f;

    int nk = K >> 5;

    float* Asw = AsBase + (size_t)srow * 36 + sc4 * 4;   // + buf*128*36
    float* Bsw = BsBase + (size_t)srow * 36 + sc4 * 4;

    auto stage = [&](int kt, int buf) {
        const float* a = Aab + (size_t)kt * 32;
        const float* b = Bab + (size_t)kt * 32;
        float* ad = Asw + (size_t)buf * 128 * 36;
        float* bd = Bsw + (size_t)buf * 128 * 36;
        #pragma unroll
        for (int q = 0; q < 2; q++) {
            cp16(smem_u32(ad + q * 4), a + q * 4, 16);
            cp16(smem_u32(bd + q * 4), b + q * 4, nvbytes);
        }
        asm volatile("cp.async.commit_group;" ::: "memory");
    };

    stage(0, 0);

    for (int kt = 0; kt < nk; kt++) {
        int buf = kt & 1;
        asm volatile("cp.async.wait_group 0;" ::: "memory");
        __syncthreads();
        if (kt + 1 < nk) stage(kt + 1, buf ^ 1);

        const float (*AsT)[36] = (const float(*)[36])(AsBase + (size_t)buf * 128 * 36);
        const float (*BsT)[36] = (const float(*)[36])(BsBase + (size_t)buf * 128 * 36);

        #pragma unroll
        for (int ks = 0; ks < 4; ks++) {
            int kk = ks * 8;
            uint32_t af[2][4];
            #pragma unroll
            for (int mi = 0; mi < 2; mi++) {
                int m0 = wm * 32 + mi * 16;
                af[mi][0] = f2tf32(AsT[m0 + g    ][kk + tg    ]);
                af[mi][1] = f2tf32(AsT[m0 + g + 8][kk + tg    ]);
                af[mi][2] = f2tf32(AsT[m0 + g    ][kk + tg + 4]);
                af[mi][3] = f2tf32(AsT[m0 + g + 8][kk + tg + 4]);
            }
            uint32_t bf[4][2];
            #pragma unroll
            for (int ni = 0; ni < 4; ni++) {
                int n0 = wn * 32 + ni * 8;
                bf[ni][0] = f2tf32(BsT[n0 + g][kk + tg    ]);
                bf[ni][1] = f2tf32(BsT[n0 + g][kk + tg + 4]);
            }
            #pragma unroll
            for (int mi = 0; mi < 2; mi++)
                #pragma unroll
                for (int ni = 0; ni < 4; ni++) {
                    asm volatile(
                        "mma.sync.aligned.m16n8k8.row.col.f32.tf32.tf32.f32 "
                        "{%0,%1,%2,%3}, {%4,%5,%6,%7}, {%8,%9}, {%0,%1,%2,%3};"
                        : "+f"(acc[mi][ni][0]), "+f"(acc[mi][ni][1]),
                          "+f"(acc[mi][ni][2]), "+f"(acc[mi][ni][3])
                        : "r"(af[mi][0]), "r"(af[mi][1]), "r"(af[mi][2]), "r"(af[mi][3]),
                          "r"(bf[ni][0]), "r"(bf[ni][1]));
                }
        }
        __syncthreads();
    }

    #pragma unroll
    for (int mi = 0; mi < 2; mi++) {
        int row0 = bm * 128 + wm * 32 + mi * 16 + g;
        int row1 = row0 + 8;
        #pragma unroll
        for (int ni = 0; ni < 4; ni++) {
            int col = bn * 128 + wn * 32 + ni * 8 + tg * 2;
            if (col < N) {
                float2 v0 = make_float2(acc[mi][ni][0], acc[mi][ni][1]);
                float2 v1 = make_float2(acc[mi][ni][2], acc[mi][ni][3]);
                if (Res) {
                    float2 r0 = *(const float2*)(Res + (size_t)row0 * N + col);
                    float2 r1 = *(const float2*)(Res + (size_t)row1 * N + col);
                    v0.x += r0.x; v0.y += r0.y;
                    v1.x += r1.x; v1.y += r1.y;
                }
                *(float2*)(Cw + (size_t)row0 * N + col) = v0;
                *(float2*)(Cw + (size_t)row1 * N + col) = v1;
            }
        }
    }
}

// ---------------- silu(gate) * up, in place into gate ----------------
__global__ void act_k(float* __restrict__ g, const float* __restrict__ u, int n) {
    int idx = blockIdx.x * blockDim.x + threadIdx.x;
    if (idx >= n) return;
    float x = g[idx];
    g[idx] = siluf(x) * u[idx];
}

// ---------------- host launcher ----------------
extern "C" void kernel_launch(void* const* d_in, const int* in_sizes, int n_in,
                              void* d_out, int out_size) {
    const float* hid        = (const float*)d_in[0];
    const float* norm_w     = (const float*)d_in[1];
    const float* in_proj_w  = (const float*)d_in[2];
    const float* conv_w     = (const float*)d_in[3];
    const float* conv_b     = (const float*)d_in[4];
    const float* dt_bias    = (const float*)d_in[5];
    const float* A_log      = (const float*)d_in[6];
    const float* Dv         = (const float*)d_in[7];
    const float* ssm_norm_w = (const float*)d_in[8];
    const float* out_proj_w = (const float*)d_in[9];
    const float* post_norm_w= (const float*)d_in[10];
    const float* gate_w     = (const float*)d_in[11];
    const float* up_w       = (const float*)d_in[12];
    const float* down_w     = (const float*)d_in[13];
    float* out = (float*)d_out;

    float *p_xn, *p_zx, *p_cv, *p_y0, *p_y1, *p_y2, *p_y3, *p_yn, *p_x2, *p_hn,
          *p_gate, *p_up;
    cudaGetSymbolAddress((void**)&p_xn,   g_xn);
    cudaGetSymbolAddress((void**)&p_zx,   g_zx);
    cudaGetSymbolAddress((void**)&p_cv,   g_cv);
    cudaGetSymbolAddress((void**)&p_y0,   g_y0);
    cudaGetSymbolAddress((void**)&p_y1,   g_y1);
    cudaGetSymbolAddress((void**)&p_y2,   g_y2);
    cudaGetSymbolAddress((void**)&p_y3,   g_y3);
    cudaGetSymbolAddress((void**)&p_yn,   g_yn);
    cudaGetSymbolAddress((void**)&p_x2,   g_x2);
    cudaGetSymbolAddress((void**)&p_hn,   g_hn);
    cudaGetSymbolAddress((void**)&p_gate, g_gate);
    cudaGetSymbolAddress((void**)&p_up,   g_up);

    static int smem_set = 0;
    if (!smem_set) {
        cudaFuncSetAttribute(gemm_tf32, cudaFuncAttributeMaxDynamicSharedMemorySize,
                             GEMM_SMEM);
        smem_set = 1;
    }

    // 1. pre-norm
    rmsnorm1024_k<<<T_, 256>>>(hid, norm_w, p_xn);
    // 2. in_proj
    gemm_tf32<<<dim3(35, 16), 512, GEMM_SMEM>>>(p_xn, in_proj_w, in_proj_w, nullptr,
                                                p_zx, p_zx, T_, DPROJ, DM, NOSPLIT);
    // 3. conv + silu
    conv_k<<<(T_ * CONVD + 255) / 256, 256>>>(p_zx, conv_w, conv_b, p_cv);
    // 4. selective scan (4-way state split, partial outputs)
    scan_k<<<512, 256>>>(p_cv, p_zx, dt_bias, A_log, Dv, p_y0, p_y1, p_y2, p_y3);
    // 5. gated rmsnorm (sums partials)
    gated_norm_k<<<T_, 256>>>(p_y0, p_y1, p_y2, p_y3, p_zx, ssm_norm_w, p_yn);
    // 6. out_proj + residual
    gemm_tf32<<<dim3(8, 16), 512, GEMM_SMEM>>>(p_yn, out_proj_w, out_proj_w, hid,
                                               p_x2, p_x2, T_, DM, DIN, NOSPLIT);
    // 7. post-norm
    rmsnorm1024_k<<<T_, 256>>>(p_x2, post_norm_w, p_hn);
    // 8. gate & up projections, fused into ONE launch (wave packing)
    gemm_tf32<<<dim3(44, 16), 512, GEMM_SMEM>>>(p_hn, gate_w, up_w, nullptr,
                                                p_gate, p_up, T_, INTER, DM, 22);
    // 9. silu(gate) * up
    act_k<<<(T_ * INTER + 255) / 256, 256>>>(p_gate, p_up, T_ * INTER);
    // 10. down projection + residual -> output
    gemm_tf32<<<dim3(8, 16), 512, GEMM_SMEM>>>(p_gate, down_w, down_w, p_x2,
                                               out, out, T_, DM, INTER, NOSPLIT);
}